// round 1
// baseline (speedup 1.0000x reference)
#include <cuda_runtime.h>
#include <math.h>

// ---------------------------------------------------------------------------
// WriteAngleParameters: triplet gather + MLP
//   x  = concat(h[i0], h[i1], h[i2])            [768]
//   z  = elu(x@W0 + b0)                          [64]
//   z  = elu((z@Ws+bs) + (elu(z@W1+b1)@W2+b2))   [64]  (residual dense)
//   z  = elu(z@W3 + b3)                          [64]
//   c  = z@W4 + b4                               [2]
//   out = [ pi*sigmoid(c0*EQ_STD/pi), K_STD*elu(c1 + K_MEAN/K_STD) ]
// ---------------------------------------------------------------------------

namespace {

constexpr int REP      = 256;
constexpr int BW       = 64;     // BETWEEN
constexpr int TILE     = 256;    // triplets per CTA
constexpr int NTHREADS = 512;    // 64 triplet-groups x 8 j-lanes
constexpr int ZSTRIDE  = 66;     // padded z-row stride (floats) to dodge bank conflicts

constexpr float PI_F   = 3.14159265358979323846f;
constexpr float EQ_STD = 0.1f;
constexpr float K_MEAN = 120.0f;
constexpr float K_STD  = 50.0f;

// smem layout (floats)
constexpr int OFF_A    = 0;                         // z buffer A: TILE*ZSTRIDE
constexpr int OFF_R2   = OFF_A + TILE * ZSTRIDE;    // W0 chunk (16384) aliased with z buffer B (16896)
constexpr int OFF_WS   = OFF_R2 + TILE * ZSTRIDE;
constexpr int OFF_W1   = OFF_WS + BW * BW;
constexpr int OFF_W2   = OFF_W1 + BW * BW;
constexpr int OFF_W3   = OFF_W2 + BW * BW;
constexpr int OFF_W4   = OFF_W3 + BW * BW;          // 128
constexpr int OFF_B0   = OFF_W4 + 128;
constexpr int OFF_B1   = OFF_B0 + 64;
constexpr int OFF_BSC  = OFF_B1 + 64;               // bs + b2 combined
constexpr int OFF_B3   = OFF_BSC + 64;
constexpr int OFF_B4   = OFF_B3 + 64;               // 2, padded to 4
constexpr int OFF_IDX  = OFF_B4 + 4;                // TILE*3 ints
constexpr int SMEM_FLOATS = OFF_IDX + TILE * 3;
constexpr size_t SMEM_BYTES = (size_t)SMEM_FLOATS * sizeof(float);

__device__ __forceinline__ unsigned long long splat2(float x) {
    unsigned long long r;
    asm("mov.b64 %0, {%1, %1};" : "=l"(r) : "f"(x));
    return r;
}
__device__ __forceinline__ float2 unpack2(unsigned long long v) {
    float2 r;
    asm("mov.b64 {%0, %1}, %2;" : "=f"(r.x), "=f"(r.y) : "l"(v));
    return r;
}
#define FMA2(d, a, b) asm("fma.rn.f32x2 %0, %1, %2, %0;" : "+l"(d) : "l"(a), "l"(b))

__device__ __forceinline__ float eluf(float x) {
    return x > 0.0f ? x : expm1f(x);
}

__global__ void __launch_bounds__(NTHREADS, 1)
wap_kernel(const float* __restrict__ h,  const int* __restrict__ idxs,
           const float* __restrict__ W0, const float* __restrict__ b0,
           const float* __restrict__ Ws, const float* __restrict__ bs,
           const float* __restrict__ W1, const float* __restrict__ b1,
           const float* __restrict__ W2, const float* __restrict__ b2,
           const float* __restrict__ W3, const float* __restrict__ b3,
           const float* __restrict__ W4, const float* __restrict__ b4,
           float* __restrict__ out, int nT)
{
    extern __shared__ float smem[];
    float* sA   = smem + OFF_A;
    float* sW0  = smem + OFF_R2;   // dead after layer 0
    float* sB   = smem + OFF_R2;   // alive from layer 1 on
    float* sWs  = smem + OFF_WS;
    float* sW1  = smem + OFF_W1;
    float* sW2  = smem + OFF_W2;
    float* sW3  = smem + OFF_W3;
    float* sW4  = smem + OFF_W4;
    float* sb0  = smem + OFF_B0;
    float* sb1  = smem + OFF_B1;
    float* sbsc = smem + OFF_BSC;
    float* sb3  = smem + OFF_B3;
    float* sb4  = smem + OFF_B4;
    int*   sidx = (int*)(smem + OFF_IDX);

    const int tid = threadIdx.x;
    const int jg  = tid & 7;       // j columns jg*8 .. jg*8+7
    const int tg  = tid >> 3;      // 0..63
    const int t0  = blockIdx.x * TILE;

    // ---- stage small weights, biases, indices ----
    for (int i = tid; i < BW * BW; i += NTHREADS) {
        sWs[i] = Ws[i]; sW1[i] = W1[i]; sW2[i] = W2[i]; sW3[i] = W3[i];
    }
    if (tid < 128) sW4[tid] = W4[tid];
    if (tid < 64) {
        sb0[tid] = b0[tid]; sb1[tid] = b1[tid];
        sbsc[tid] = bs[tid] + b2[tid]; sb3[tid] = b3[tid];
    }
    if (tid < 2) sb4[tid] = b4[tid];
    for (int i = tid; i < TILE * 3; i += NTHREADS) {
        int t = t0 + i / 3;
        if (t >= nT) t = nT - 1;                 // clamp: tail triplets computed but not stored
        sidx[i] = idxs[(size_t)t * 3 + (i % 3)];
    }
    __syncthreads();

    int lt[4], ltoff[4];
    #pragma unroll
    for (int r = 0; r < 4; r++) { lt[r] = tg + 64 * r; ltoff[r] = lt[r] * ZSTRIDE; }

    // ---- layer 0: [768] -> [64], accumulate in packed f32x2 ----
    unsigned long long acc[16];
    {
        const unsigned long long* bp = (const unsigned long long*)(sb0 + jg * 8);
        #pragma unroll
        for (int c = 0; c < 4; c++) {
            unsigned long long bv = bp[c];
            acc[c] = bv; acc[4 + c] = bv; acc[8 + c] = bv; acc[12 + c] = bv;
        }
    }

    for (int n = 0; n < 3; n++) {
        __syncthreads();  // protects previous chunk's readers (no-op cost on n=0)
        {
            const float4* src = (const float4*)(W0 + (size_t)n * REP * BW);
            float4* dst = (float4*)sW0;
            for (int i = tid; i < REP * BW / 4; i += NTHREADS) dst[i] = src[i];
        }
        __syncthreads();

        const float* p[4];
        #pragma unroll
        for (int r = 0; r < 4; r++)
            p[r] = h + (size_t)sidx[lt[r] * 3 + n] * REP;

        #pragma unroll 2
        for (int k4 = 0; k4 < REP / 4; k4++) {
            float xa[4][4];
            #pragma unroll
            for (int r = 0; r < 4; r++)
                *(float4*)xa[r] = ((const float4*)p[r])[k4];
            #pragma unroll
            for (int u = 0; u < 4; u++) {
                const float* wr = sW0 + (k4 * 4 + u) * BW + jg * 8;
                ulonglong2 wa = *(const ulonglong2*)wr;
                ulonglong2 wb = *(const ulonglong2*)(wr + 4);
                #pragma unroll
                for (int r = 0; r < 4; r++) {
                    unsigned long long s = splat2(xa[r][u]);
                    FMA2(acc[4 * r + 0], wa.x, s);
                    FMA2(acc[4 * r + 1], wa.y, s);
                    FMA2(acc[4 * r + 2], wb.x, s);
                    FMA2(acc[4 * r + 3], wb.y, s);
                }
            }
        }
    }
    // elu + write z -> A
    #pragma unroll
    for (int r = 0; r < 4; r++)
        #pragma unroll
        for (int c = 0; c < 4; c++) {
            float2 v = unpack2(acc[4 * r + c]);
            v.x = eluf(v.x); v.y = eluf(v.y);
            *(float2*)(sA + ltoff[r] + jg * 8 + 2 * c) = v;
        }
    __syncthreads();   // A ready; sW0 region now reusable as B

    // ---- layer 1: t1 = elu(A@W1 + b1) -> B ----
    {
        const unsigned long long* bp = (const unsigned long long*)(sb1 + jg * 8);
        #pragma unroll
        for (int c = 0; c < 4; c++) {
            unsigned long long bv = bp[c];
            acc[c] = bv; acc[4 + c] = bv; acc[8 + c] = bv; acc[12 + c] = bv;
        }
        #pragma unroll 4
        for (int k = 0; k < BW; k++) {
            const float* wr = sW1 + k * BW + jg * 8;
            ulonglong2 wa = *(const ulonglong2*)wr;
            ulonglong2 wb = *(const ulonglong2*)(wr + 4);
            #pragma unroll
            for (int r = 0; r < 4; r++) {
                unsigned long long s = splat2(sA[ltoff[r] + k]);
                FMA2(acc[4 * r + 0], wa.x, s);
                FMA2(acc[4 * r + 1], wa.y, s);
                FMA2(acc[4 * r + 2], wb.x, s);
                FMA2(acc[4 * r + 3], wb.y, s);
            }
        }
        #pragma unroll
        for (int r = 0; r < 4; r++)
            #pragma unroll
            for (int c = 0; c < 4; c++) {
                float2 v = unpack2(acc[4 * r + c]);
                v.x = eluf(v.x); v.y = eluf(v.y);
                *(float2*)(sB + ltoff[r] + jg * 8 + 2 * c) = v;
            }
    }
    __syncthreads();   // B ready

    // ---- residual combine: z = elu(A@Ws + B@W2 + (bs+b2)) -> A ----
    {
        const unsigned long long* bp = (const unsigned long long*)(sbsc + jg * 8);
        #pragma unroll
        for (int c = 0; c < 4; c++) {
            unsigned long long bv = bp[c];
            acc[c] = bv; acc[4 + c] = bv; acc[8 + c] = bv; acc[12 + c] = bv;
        }
        #pragma unroll 4
        for (int k = 0; k < BW; k++) {
            const float* wr = sWs + k * BW + jg * 8;
            ulonglong2 wa = *(const ulonglong2*)wr;
            ulonglong2 wb = *(const ulonglong2*)(wr + 4);
            #pragma unroll
            for (int r = 0; r < 4; r++) {
                unsigned long long s = splat2(sA[ltoff[r] + k]);
                FMA2(acc[4 * r + 0], wa.x, s);
                FMA2(acc[4 * r + 1], wa.y, s);
                FMA2(acc[4 * r + 2], wb.x, s);
                FMA2(acc[4 * r + 3], wb.y, s);
            }
        }
        #pragma unroll 4
        for (int k = 0; k < BW; k++) {
            const float* wr = sW2 + k * BW + jg * 8;
            ulonglong2 wa = *(const ulonglong2*)wr;
            ulonglong2 wb = *(const ulonglong2*)(wr + 4);
            #pragma unroll
            for (int r = 0; r < 4; r++) {
                unsigned long long s = splat2(sB[ltoff[r] + k]);
                FMA2(acc[4 * r + 0], wa.x, s);
                FMA2(acc[4 * r + 1], wa.y, s);
                FMA2(acc[4 * r + 2], wb.x, s);
                FMA2(acc[4 * r + 3], wb.y, s);
            }
        }
        __syncthreads();   // everyone done reading A/B before A is overwritten
        #pragma unroll
        for (int r = 0; r < 4; r++)
            #pragma unroll
            for (int c = 0; c < 4; c++) {
                float2 v = unpack2(acc[4 * r + c]);
                v.x = eluf(v.x); v.y = eluf(v.y);
                *(float2*)(sA + ltoff[r] + jg * 8 + 2 * c) = v;
            }
    }
    __syncthreads();   // new A ready

    // ---- layer 3: z = elu(A@W3 + b3) -> B ----
    {
        const unsigned long long* bp = (const unsigned long long*)(sb3 + jg * 8);
        #pragma unroll
        for (int c = 0; c < 4; c++) {
            unsigned long long bv = bp[c];
            acc[c] = bv; acc[4 + c] = bv; acc[8 + c] = bv; acc[12 + c] = bv;
        }
        #pragma unroll 4
        for (int k = 0; k < BW; k++) {
            const float* wr = sW3 + k * BW + jg * 8;
            ulonglong2 wa = *(const ulonglong2*)wr;
            ulonglong2 wb = *(const ulonglong2*)(wr + 4);
            #pragma unroll
            for (int r = 0; r < 4; r++) {
                unsigned long long s = splat2(sA[ltoff[r] + k]);
                FMA2(acc[4 * r + 0], wa.x, s);
                FMA2(acc[4 * r + 1], wa.y, s);
                FMA2(acc[4 * r + 2], wb.x, s);
                FMA2(acc[4 * r + 3], wb.y, s);
            }
        }
        #pragma unroll
        for (int r = 0; r < 4; r++)
            #pragma unroll
            for (int c = 0; c < 4; c++) {
                float2 v = unpack2(acc[4 * r + c]);
                v.x = eluf(v.x); v.y = eluf(v.y);
                *(float2*)(sB + ltoff[r] + jg * 8 + 2 * c) = v;
            }
    }
    __syncthreads();   // final z in B

    // ---- head: c = z@W4 + b4, output transforms ----
    if (jg == 0) {
        #pragma unroll
        for (int r = 0; r < 4; r++) {
            int t = t0 + lt[r];
            if (t < nT) {
                float c0 = sb4[0], c1 = sb4[1];
                #pragma unroll 8
                for (int k = 0; k < BW; k++) {
                    float z = sB[ltoff[r] + k];
                    c0 += z * sW4[2 * k];
                    c1 += z * sW4[2 * k + 1];
                }
                float eq = PI_F / (1.0f + expf(-c0 * (EQ_STD / PI_F)));
                float kk = K_STD * eluf(c1 + K_MEAN / K_STD);
                *(float2*)(out + (size_t)t * 2) = make_float2(eq, kk);
            }
        }
    }
}

} // namespace

extern "C" void kernel_launch(void* const* d_in, const int* in_sizes, int n_in,
                              void* d_out, int out_size) {
    const float* h   = (const float*)d_in[0];
    const int*   idx = (const int*)  d_in[1];
    const float* W0  = (const float*)d_in[2];
    const float* b0  = (const float*)d_in[3];
    const float* Ws  = (const float*)d_in[4];
    const float* bs  = (const float*)d_in[5];
    const float* W1  = (const float*)d_in[6];
    const float* b1  = (const float*)d_in[7];
    const float* W2  = (const float*)d_in[8];
    const float* b2  = (const float*)d_in[9];
    const float* W3  = (const float*)d_in[10];
    const float* b3  = (const float*)d_in[11];
    const float* W4  = (const float*)d_in[12];
    const float* b4  = (const float*)d_in[13];
    float* out = (float*)d_out;

    int nT = in_sizes[1] / 3;
    int grid = (nT + TILE - 1) / TILE;

    cudaFuncSetAttribute(wap_kernel,
                         cudaFuncAttributeMaxDynamicSharedMemorySize,
                         (int)SMEM_BYTES);
    wap_kernel<<<grid, NTHREADS, SMEM_BYTES>>>(
        h, idx, W0, b0, Ws, bs, W1, b1, W2, b2, W3, b3, W4, b4, out, nT);
    (void)n_in; (void)out_size;
}